// round 1
// baseline (speedup 1.0000x reference)
#include <cuda_runtime.h>
#include <cstdint>

// Problem constants (fixed by the dataset)
#define NN 10000     // nodes
#define FF 128       // feature dim
#define BT 4         // B*T
#define EE 160000    // edges
#define NLAYERS 2

// Persistent device scratch (no allocations allowed in kernel_launch)
__device__ float g_h[(size_t)BT * NN * FF];     // hidden state between layers
__device__ float g_agg[(size_t)BT * NN * FF];   // per-layer aggregation buffer
__device__ float g_deg[NN];
__device__ float g_invdeg[NN];

// ---------------------------------------------------------------------------
// Zeroing kernels (memset via kernel keeps us free of symbol-address host APIs)
// ---------------------------------------------------------------------------
__global__ void zero_deg_kernel() {
    int i = blockIdx.x * blockDim.x + threadIdx.x;
    if (i < NN) g_deg[i] = 0.0f;
}

__global__ void zero_agg_kernel() {
    // BT*NN*FF = 5,120,000 floats = 1,280,000 float4
    int i = blockIdx.x * blockDim.x + threadIdx.x;
    float4* p = reinterpret_cast<float4*>(g_agg);
    if (i < (BT * NN * FF) / 4) p[i] = make_float4(0.f, 0.f, 0.f, 0.f);
}

// ---------------------------------------------------------------------------
// Degree + inverse degree
// ---------------------------------------------------------------------------
__global__ void deg_kernel(const int* __restrict__ edge_dst) {
    int e = blockIdx.x * blockDim.x + threadIdx.x;
    if (e < EE) atomicAdd(&g_deg[edge_dst[e]], 1.0f);
}

__global__ void invdeg_kernel() {
    int n = blockIdx.x * blockDim.x + threadIdx.x;
    if (n < NN) {
        float d = g_deg[n];
        g_invdeg[n] = (d > 0.0f) ? (1.0f / d) : 0.0f;
    }
}

// ---------------------------------------------------------------------------
// Scatter: agg[bt][dst][:] += X[bt][src][:]  for every edge.
// One thread per (edge, bt, 4-float chunk): E*4*32 = 20.48M threads.
// A warp = one (edge, bt): 32 lanes read a contiguous 512B row (coalesced,
// L2-resident) and issue one red.global.add.v4.f32 each (16B vector atomic).
// ---------------------------------------------------------------------------
__global__ void scatter_kernel(const float* __restrict__ Xin,
                               const int* __restrict__ edge_src,
                               const int* __restrict__ edge_dst,
                               int layer) {
    const float* __restrict__ X = (layer == 0) ? Xin : g_h;
    int idx  = blockIdx.x * blockDim.x + threadIdx.x;   // < EE*128
    int e    = idx >> 7;
    int r    = idx & 127;
    int bt   = r >> 5;
    int lane = r & 31;

    int s = edge_src[e];
    int d = edge_dst[e];

    const float4* xs = reinterpret_cast<const float4*>(
        X + ((size_t)bt * NN + s) * FF);
    float4 v = xs[lane];

    float* ap = g_agg + ((size_t)bt * NN + d) * FF + lane * 4;
    asm volatile("red.global.add.v4.f32 [%0], {%1, %2, %3, %4};"
                 :: "l"(ap), "f"(v.x), "f"(v.y), "f"(v.z), "f"(v.w)
                 : "memory");
}

// ---------------------------------------------------------------------------
// Fused GEMM: Y[bt][n][g] = sum_f X[bt][n][f]*Ws[f][g]
//                         + inv_deg[n] * sum_f agg[bt][n][f]*Wn[f][g]
//                         + bias[g]
// Tiling: block = 256 threads computes 64 rows x 128 cols, K-tiled by 16.
// A tiles stored k-major with pad 68 so each thread does 4x LDS.128 + 64 FFMA
// per k-step (LDS bandwidth 64B per 64 FMA << 128B/cyc crossbar).
// ---------------------------------------------------------------------------
#define TM 64
#define TK 16
#define APAD 68   // multiple of 4 (16B-aligned float4 rows), bank stride 4

__global__ __launch_bounds__(256) void gemm_kernel(
    const float* __restrict__ Xin,          // feature (used when layer==0)
    const float* __restrict__ W_self,
    const float* __restrict__ W_neigh,
    const float* __restrict__ bias_all,
    float* __restrict__ Yout,               // d_out (used when layer==last)
    int layer) {

    const float* __restrict__ X  = (layer == 0) ? Xin : g_h;
    float* __restrict__ Y        = (layer == NLAYERS - 1) ? Yout : g_h;
    const float* __restrict__ Ws = W_self  + (size_t)layer * FF * FF;
    const float* __restrict__ Wn = W_neigh + (size_t)layer * FF * FF;
    const float* __restrict__ bs = bias_all + (size_t)layer * FF;

    __shared__ float As[TK * APAD];
    __shared__ float An[TK * APAD];
    __shared__ float Ws_s[TK * FF];
    __shared__ float Wn_s[TK * FF];

    const int t  = threadIdx.x;
    const int c0 = (t & 31) * 4;        // 4 contiguous output cols
    const int r0 = (t >> 5) * 8;        // 8 contiguous rows
    const int m0 = blockIdx.x * TM;
    const int bt = blockIdx.y;

    float acc[8][4];
    #pragma unroll
    for (int i = 0; i < 8; i++)
        #pragma unroll
        for (int j = 0; j < 4; j++) acc[i][j] = 0.0f;

    for (int k0 = 0; k0 < FF; k0 += TK) {
        // Load weight tiles: 16x128 each, 8 elems/thread, coalesced.
        #pragma unroll
        for (int i = 0; i < 8; i++) {
            int idx = t + i * 256;
            int kk = idx >> 7, c = idx & 127;
            Ws_s[kk * FF + c] = Ws[(size_t)(k0 + kk) * FF + c];
            Wn_s[kk * FF + c] = Wn[(size_t)(k0 + kk) * FF + c];
        }
        // Load A tiles (transposed to k-major), 4 elems/thread.
        #pragma unroll
        for (int i = 0; i < 4; i++) {
            int idx = t + i * 256;
            int mm = idx >> 4, kk = idx & 15;
            int row = m0 + mm;
            float xv = 0.0f, av = 0.0f;
            if (row < NN) {
                size_t off = ((size_t)bt * NN + row) * FF + (k0 + kk);
                xv = X[off];
                av = g_agg[off] * g_invdeg[row];
            }
            As[kk * APAD + mm] = xv;
            An[kk * APAD + mm] = av;
        }
        __syncthreads();

        #pragma unroll
        for (int kk = 0; kk < TK; kk++) {
            float4 a0 = *reinterpret_cast<const float4*>(&As[kk * APAD + r0]);
            float4 a1 = *reinterpret_cast<const float4*>(&As[kk * APAD + r0 + 4]);
            float4 n0 = *reinterpret_cast<const float4*>(&An[kk * APAD + r0]);
            float4 n1 = *reinterpret_cast<const float4*>(&An[kk * APAD + r0 + 4]);
            float4 w0 = *reinterpret_cast<const float4*>(&Ws_s[kk * FF + c0]);
            float4 w1 = *reinterpret_cast<const float4*>(&Wn_s[kk * FF + c0]);

            float a[8]  = {a0.x, a0.y, a0.z, a0.w, a1.x, a1.y, a1.z, a1.w};
            float an[8] = {n0.x, n0.y, n0.z, n0.w, n1.x, n1.y, n1.z, n1.w};
            float ws[4] = {w0.x, w0.y, w0.z, w0.w};
            float wn[4] = {w1.x, w1.y, w1.z, w1.w};

            #pragma unroll
            for (int i = 0; i < 8; i++)
                #pragma unroll
                for (int j = 0; j < 4; j++)
                    acc[i][j] += a[i] * ws[j] + an[i] * wn[j];
        }
        __syncthreads();
    }

    // Epilogue: add bias, store float4. Output layout == [bt][n][f] == [B,T,N,F].
    float4 bb = *reinterpret_cast<const float4*>(&bs[c0]);
    #pragma unroll
    for (int i = 0; i < 8; i++) {
        int row = m0 + r0 + i;
        if (row < NN) {
            float4 o;
            o.x = acc[i][0] + bb.x;
            o.y = acc[i][1] + bb.y;
            o.z = acc[i][2] + bb.z;
            o.w = acc[i][3] + bb.w;
            *reinterpret_cast<float4*>(
                &Y[((size_t)bt * NN + row) * FF + c0]) = o;
        }
    }
}

// ---------------------------------------------------------------------------
// Launch
// ---------------------------------------------------------------------------
extern "C" void kernel_launch(void* const* d_in, const int* in_sizes, int n_in,
                              void* d_out, int out_size) {
    const float* feature = (const float*)d_in[0];   // [B,T,N,F] == [bt][n][f]
    const float* W_self  = (const float*)d_in[1];   // [L,F,F]
    const float* W_neigh = (const float*)d_in[2];   // [L,F,F]
    const float* bias    = (const float*)d_in[3];   // [L,F]
    const int*   esrc    = (const int*)d_in[4];     // [E]
    const int*   edst    = (const int*)d_in[5];     // [E]
    float* out = (float*)d_out;                     // [B,T,N,F]

    // Degree (recomputed every call; deterministic work)
    zero_deg_kernel<<<(NN + 255) / 256, 256>>>();
    deg_kernel<<<(EE + 255) / 256, 256>>>(edst);
    invdeg_kernel<<<(NN + 255) / 256, 256>>>();

    const int scatter_blocks = (EE * 128) / 256;           // 80000
    const int agg_blocks     = (BT * NN * FF / 4 + 255) / 256;
    dim3 ggrid((NN + TM - 1) / TM, BT);                    // (157, 4)

    for (int layer = 0; layer < NLAYERS; layer++) {
        zero_agg_kernel<<<agg_blocks, 256>>>();
        scatter_kernel<<<scatter_blocks, 256>>>(feature, esrc, edst, layer);
        gemm_kernel<<<ggrid, 256>>>(feature, W_self, W_neigh, bias, out, layer);
    }
}